// round 11
// baseline (speedup 1.0000x reference)
#include <cuda_runtime.h>
#include <cuda_bf16.h>
#include <float.h>
#include <stdint.h>

#define DDIM   64
#define KCODES 512
#define RB     128
#define NROWS  65536
#define APITCH 272      // 128 bf16 + pad; 272B = 68 words -> 4-bank row rotation, LDSM conflict-free
#define BPITCH 272
#define MARGIN 0.25f

// -------- output layout -----------------------------------------------------
#define OFF_Q    0
#define OFF_DIFF 4194304
#define OFF_IND  4194305
#define OFF_EN   4259841
#define OFF_NCS  4292609
#define OFF_NEA  4293121

// -------- device scratch ----------------------------------------------------
__device__ float  g_esum[DDIM * KCODES];
__device__ float  g_cnt[KCODES];
__device__ float  g_e2[KCODES];
__device__ double g_diff;
__device__ int    g_kbest[NROWS];
__device__ int    g_flagcnt;
__device__ int    g_flagrows[NROWS];
__device__ unsigned long long g_ebu[KCODES * 32];   // bf16 [n][128] = 2 planes

// -------- dynamic smem ------------------------------------------------------
#define SM_E2   0                       // f32[512]
#define SM_A    3072                    // 128 x 272 = 34816
#define SM_B    37888                   // 256 x 272 = 69632
#define SMEM_TOTAL 107520

__device__ __forceinline__ uint32_t smem_u32(const void* p) {
    uint32_t a;
    asm("{ .reg .u64 t; cvta.to.shared.u64 t, %1; cvt.u32.u64 %0, t; }" : "=r"(a) : "l"(p));
    return a;
}
__device__ __forceinline__ void ldsm_x4(uint32_t* r, uint32_t addr) {
    asm volatile("ldmatrix.sync.aligned.m8n8.x4.shared.b16 {%0,%1,%2,%3}, [%4];"
                 : "=r"(r[0]), "=r"(r[1]), "=r"(r[2]), "=r"(r[3]) : "r"(addr));
}
__device__ __forceinline__ void ldsm_x2(uint32_t* r, uint32_t addr) {
    asm volatile("ldmatrix.sync.aligned.m8n8.x2.shared.b16 {%0,%1}, [%2];"
                 : "=r"(r[0]), "=r"(r[1]) : "r"(addr));
}
#define MMA(C, A, B)                                                               \
    asm volatile("mma.sync.aligned.m16n8k16.row.col.f32.bf16.bf16.f32 "            \
                 "{%0,%1,%2,%3},{%4,%5,%6,%7},{%8,%9},{%0,%1,%2,%3};"              \
                 : "+f"((C)[0]), "+f"((C)[1]), "+f"((C)[2]), "+f"((C)[3])          \
                 : "r"((A)[0]), "r"((A)[1]), "r"((A)[2]), "r"((A)[3]),             \
                   "r"((B)[0]), "r"((B)[1]))

// ============================================================================
// Kernel 0: zero scratch, split embed -> bf16x2 [n][p*64+d], exact ||e||^2
// ============================================================================
__global__ void prep_kernel(const float* __restrict__ embed) {
    int t = blockIdx.x * blockDim.x + threadIdx.x;
    if (t < DDIM * KCODES) {
        g_esum[t] = 0.0f;
        float x = embed[t];                       // [d][n]
        int d = t >> 9, n = t & 511;
        __nv_bfloat16 b0 = __float2bfloat16(x);
        float r1 = x - __bfloat162float(b0);
        __nv_bfloat16 b1 = __float2bfloat16(r1);
        __nv_bfloat16* eb = (__nv_bfloat16*)g_ebu;
        eb[n * 128 +      d] = b0;
        eb[n * 128 + 64 + d] = b1;
    }
    if (t < KCODES) {
        g_cnt[t] = 0.0f;
        float s = 0.0f;
        #pragma unroll 8
        for (int d = 0; d < DDIM; d++) {
            float e = embed[d * KCODES + t];
            s = fmaf(e, e, s);
        }
        g_e2[t] = s;
    }
    if (t == 0) { g_diff = 0.0; g_flagcnt = 0; }
}

// ============================================================================
// Kernel 1: phase-1 3-term HMMA distance GEMM + top-2 argmin + margin flagging
// ============================================================================
__global__ __launch_bounds__(256, 2) void vq_main(const float* __restrict__ input) {
    extern __shared__ char smem[];
    const uint32_t sb = smem_u32(smem);
    float* sE2 = (float*)(smem + SM_E2);

    const int tid = threadIdx.x;
    const int wid = tid >> 5, lane = tid & 31;
    const int r0 = blockIdx.x * RB;

    sE2[tid]       = g_e2[tid];
    sE2[tid + 256] = g_e2[tid + 256];

    // ---- split A rows -> 2 bf16 planes [m][p*64+d], pitch 272 ----
    #pragma unroll
    for (int i = 0; i < 16; i++) {
        int e = tid + 256 * i;                 // 4096 d-pairs
        int m = e >> 5, d0 = (e & 31) * 2;
        float2 v = *(const float2*)&input[(size_t)(r0 + m) * DDIM + d0];
        __nv_bfloat16 p0a = __float2bfloat16(v.x), p0b = __float2bfloat16(v.y);
        float r1a = v.x - __bfloat162float(p0a), r1b = v.y - __bfloat162float(p0b);
        __nv_bfloat16 p1a = __float2bfloat16(r1a), p1b = __float2bfloat16(r1b);
        char* row = smem + SM_A + m * APITCH;
        *(uint32_t*)(row +       d0 * 2) = (uint32_t)__bfloat16_as_ushort(p0a) | ((uint32_t)__bfloat16_as_ushort(p0b) << 16);
        *(uint32_t*)(row + 128 + d0 * 2) = (uint32_t)__bfloat16_as_ushort(p1a) | ((uint32_t)__bfloat16_as_ushort(p1b) << 16);
    }
    __syncthreads();

    // ---- hoist A fragments: af[p*4+s][4] ----
    uint32_t af[8][4];
    {
        int t4 = lane >> 3, rlo = lane & 7;
        int mrow = wid * 16 + ((t4 & 1) << 3) + rlo;
        int koff = (t4 >> 1) << 3;
        #pragma unroll
        for (int p = 0; p < 2; p++)
            #pragma unroll
            for (int s = 0; s < 4; s++)
                ldsm_x4(af[p * 4 + s], sb + SM_A + mrow * APITCH + (p * 64 + s * 16 + koff) * 2);
    }

    float bv0 = FLT_MAX, sv0 = FLT_MAX, bv1 = FLT_MAX, sv1 = FLT_MAX;
    int   bk0 = 0x7fffffff, bk1 = 0x7fffffff;

    for (int chunk = 0; chunk < 2; chunk++) {
        // ---- stage B chunk: 256 codes x 128 bf16 ----
        #pragma unroll
        for (int i = 0; i < 32; i++) {
            int u = tid + 256 * i;             // 8192 u64
            int n = u >> 5, q = u & 31;
            *(unsigned long long*)(smem + SM_B + n * BPITCH + q * 8) =
                g_ebu[(size_t)(chunk * 256 + n) * 32 + q];
        }
        __syncthreads();

        for (int nt = 0; nt < 32; nt += 2) {
            uint32_t bf[2][8][2];
            {
                int rlo = lane & 7, khalf = ((lane >> 3) & 1) << 3;
                #pragma unroll
                for (int u = 0; u < 2; u++)
                    #pragma unroll
                    for (int p = 0; p < 2; p++)
                        #pragma unroll
                        for (int s = 0; s < 4; s++)
                            ldsm_x2(bf[u][p * 4 + s],
                                    sb + SM_B + ((nt + u) * 8 + rlo) * BPITCH +
                                    (p * 64 + s * 16 + khalf) * 2);
            }
            float Cc[2][2][4];
            #pragma unroll
            for (int u = 0; u < 2; u++)
                #pragma unroll
                for (int c = 0; c < 2; c++)
                    #pragma unroll
                    for (int j = 0; j < 4; j++) Cc[u][c][j] = 0.0f;

            // 24 MMAs: terms a0b0 + a1b0 (chain0), a0b1 (chain1), 2 n-tiles
            #pragma unroll
            for (int s = 0; s < 4; s++) {
                MMA(Cc[0][0], af[s], bf[0][s]);
                MMA(Cc[0][1], af[s], bf[0][4 + s]);
                MMA(Cc[1][0], af[s], bf[1][s]);
                MMA(Cc[1][1], af[s], bf[1][4 + s]);
            }
            #pragma unroll
            for (int s = 0; s < 4; s++) {
                MMA(Cc[0][0], af[4 + s], bf[0][s]);
                MMA(Cc[1][0], af[4 + s], bf[1][s]);
            }

            // ---- distances + top-2 (k strictly ascending per thread) ----
            #pragma unroll
            for (int u = 0; u < 2; u++) {
                int nb = chunk * 256 + (nt + u) * 8 + 2 * (lane & 3);
                float e2a = sE2[nb], e2b = sE2[nb + 1];
                float d00 = e2a - 2.0f * (Cc[u][0][0] + Cc[u][1][0]);
                float d01 = e2b - 2.0f * (Cc[u][0][1] + Cc[u][1][1]);
                float d10 = e2a - 2.0f * (Cc[u][0][2] + Cc[u][1][2]);
                float d11 = e2b - 2.0f * (Cc[u][0][3] + Cc[u][1][3]);
                if (d00 < bv0) { sv0 = bv0; bv0 = d00; bk0 = nb; } else if (d00 < sv0) sv0 = d00;
                if (d01 < bv0) { sv0 = bv0; bv0 = d01; bk0 = nb + 1; } else if (d01 < sv0) sv0 = d01;
                if (d10 < bv1) { sv1 = bv1; bv1 = d10; bk1 = nb; } else if (d10 < sv1) sv1 = d10;
                if (d11 < bv1) { sv1 = bv1; bv1 = d11; bk1 = nb + 1; } else if (d11 < sv1) sv1 = d11;
            }
        }
        __syncthreads();   // B readers done before next chunk overwrite
    }

    // ---- merge top-2 across the 4 lanes sharing each row ----
    #pragma unroll
    for (int off = 1; off <= 2; off <<= 1) {
        float ov0 = __shfl_xor_sync(0xffffffffu, bv0, off);
        int   ok0 = __shfl_xor_sync(0xffffffffu, bk0, off);
        float os0 = __shfl_xor_sync(0xffffffffu, sv0, off);
        float ov1 = __shfl_xor_sync(0xffffffffu, bv1, off);
        int   ok1 = __shfl_xor_sync(0xffffffffu, bk1, off);
        float os1 = __shfl_xor_sync(0xffffffffu, sv1, off);
        if (ov0 < bv0 || (ov0 == bv0 && ok0 < bk0)) { sv0 = fminf(bv0, os0); bv0 = ov0; bk0 = ok0; }
        else sv0 = fminf(sv0, fminf(ov0, os0));
        if (ov1 < bv1 || (ov1 == bv1 && ok1 < bk1)) { sv1 = fminf(bv1, os1); bv1 = ov1; bk1 = ok1; }
        else sv1 = fminf(sv1, fminf(ov1, os1));
    }
    if ((lane & 3) == 0) {
        int rq = r0 + wid * 16 + (lane >> 2);
        g_kbest[rq] = bk0;
        if (sv0 - bv0 <= MARGIN) g_flagrows[atomicAdd(&g_flagcnt, 1)] = rq;
        g_kbest[rq + 8] = bk1;
        if (sv1 - bv1 <= MARGIN) g_flagrows[atomicAdd(&g_flagcnt, 1)] = rq + 8;
    }
}

// ============================================================================
// Kernel 2: rescue — exact fp32 argmin for flagged rows (ref tie-break)
// ============================================================================
__global__ void rescue_kernel(const float* __restrict__ input,
                              const float* __restrict__ embed) {
    const int lane = threadIdx.x & 31;
    const int gw = blockIdx.x * (blockDim.x >> 5) + (threadIdx.x >> 5);
    const int nw = gridDim.x * (blockDim.x >> 5);
    const int nflag = g_flagcnt;

    for (int i = gw; i < nflag; i += nw) {
        int row = g_flagrows[i];
        float xa = input[(size_t)row * DDIM + lane];
        float xb = input[(size_t)row * DDIM + 32 + lane];
        float acc[16];
        #pragma unroll
        for (int j = 0; j < 16; j++) acc[j] = 0.0f;
        for (int d = 0; d < DDIM; d++) {
            float xd = (d < 32) ? __shfl_sync(0xffffffffu, xa, d)
                                : __shfl_sync(0xffffffffu, xb, d - 32);
            const float* er = embed + d * KCODES + lane;
            #pragma unroll
            for (int j = 0; j < 16; j++) acc[j] = fmaf(xd, er[32 * j], acc[j]);
        }
        float bv = FLT_MAX; int bk = 0x7fffffff;
        #pragma unroll
        for (int j = 0; j < 16; j++) {
            int k = lane + 32 * j;
            float dist = g_e2[k] - 2.0f * acc[j];
            if (dist < bv) { bv = dist; bk = k; }   // k ascending per lane
        }
        #pragma unroll
        for (int off = 16; off; off >>= 1) {
            float ov = __shfl_xor_sync(0xffffffffu, bv, off);
            int   ok = __shfl_xor_sync(0xffffffffu, bk, off);
            if (ov < bv || (ov == bv && ok < bk)) { bv = ov; bk = ok; }
        }
        if (lane == 0) g_kbest[row] = bk;
    }
}

// ============================================================================
// Kernel 3: epilogue — quantize_st, IND, scatter, diff
// ============================================================================
__global__ void epilogue_kernel(const float* __restrict__ input,
                                const float* __restrict__ embed,
                                float* __restrict__ out) {
    const int lane = threadIdx.x & 31;
    const int gw = blockIdx.x * 8 + (threadIdx.x >> 5);
    double dsum = 0.0;
    #pragma unroll
    for (int j = 0; j < 8; j++) {
        int row = gw * 8 + j;
        int kbest = g_kbest[row];
        if (lane == 0) {
            out[OFF_IND + row] = (float)kbest;
            atomicAdd(&g_cnt[kbest], 1.0f);
        }
        #pragma unroll
        for (int h = 0; h < 2; h++) {
            int d = lane + 32 * h;
            float x = input[(size_t)row * DDIM + d];
            float q = embed[d * KCODES + kbest];
            out[OFF_Q + (size_t)row * DDIM + d] = x + (q - x);
            float df = q - x;
            dsum += (double)df * (double)df;
            atomicAdd(&g_esum[d * KCODES + kbest], x);
        }
    }
    #pragma unroll
    for (int off = 16; off; off >>= 1)
        dsum += __shfl_xor_sync(0xffffffffu, dsum, off);
    if (lane == 0) atomicAdd(&g_diff, dsum);
}

// ============================================================================
// Kernel 4: EMA update + normalize + diff mean
// ============================================================================
__global__ void vq_finalize(const float* __restrict__ cluster_size,
                            const float* __restrict__ embed_avg,
                            float* __restrict__ out) {
    __shared__ float red[512];
    const int k = threadIdx.x;
    const float DEC = 0.99f;
    const float OMD = (float)(1.0 - 0.99);

    float ncs = cluster_size[k] * DEC + OMD * g_cnt[k];
    out[OFF_NCS + k] = ncs;
    red[k] = ncs;
    __syncthreads();
    for (int s = 256; s; s >>= 1) {
        if (k < s) red[k] += red[k + s];
        __syncthreads();
    }
    float n  = red[0];
    float cs = (ncs + 1e-5f) / (n + 512.0f * 1e-5f) * n;

    for (int d = 0; d < DDIM; d++) {
        int idx = d * KCODES + k;
        float nea = embed_avg[idx] * DEC + OMD * g_esum[idx];
        out[OFF_NEA + idx] = nea;
        out[OFF_EN  + idx] = nea / cs;
    }
    if (k == 0) out[OFF_DIFF] = (float)(g_diff * (1.0 / 4194304.0));
}

// ============================================================================
extern "C" void kernel_launch(void* const* d_in, const int* in_sizes, int n_in,
                              void* d_out, int out_size) {
    const float* input        = (const float*)d_in[0];
    const float* embed        = (const float*)d_in[1];
    const float* cluster_size = (const float*)d_in[2];
    const float* embed_avg    = (const float*)d_in[3];
    float* out = (float*)d_out;

    cudaFuncSetAttribute(vq_main, cudaFuncAttributeMaxDynamicSharedMemorySize, SMEM_TOTAL);
    prep_kernel<<<128, 256>>>(embed);
    vq_main<<<512, 256, SMEM_TOTAL>>>(input);
    rescue_kernel<<<256, 256>>>(input, embed);
    epilogue_kernel<<<1024, 256>>>(input, embed, out);
    vq_finalize<<<1, 512>>>(cluster_size, embed_avg, out);
}

// round 12
// speedup vs baseline: 1.1441x; 1.1441x over previous
#include <cuda_runtime.h>
#include <cuda_bf16.h>
#include <float.h>
#include <stdint.h>

#define DDIM   64
#define KCODES 512
#define RB     128
#define NROWS  65536
#define APITCH 272
#define BPITCH 272
#define MARGIN 0.25f
#define NPART  4

// -------- output layout -----------------------------------------------------
#define OFF_Q    0
#define OFF_DIFF 4194304
#define OFF_IND  4194305
#define OFF_EN   4259841
#define OFF_NCS  4292609
#define OFF_NEA  4293121

// -------- device scratch ----------------------------------------------------
__device__ __align__(16) float g_esumT[NPART][KCODES * DDIM];  // [part][k][d]
__device__ __align__(16) float g_embT[KCODES * DDIM];          // fp32 [k][d]
__device__ float  g_cnt[KCODES];
__device__ float  g_e2[KCODES];
__device__ double g_diff;
__device__ int    g_kbest[NROWS];
__device__ int    g_flagcnt;
__device__ int    g_flagrows[NROWS];
__device__ unsigned long long g_ebu[KCODES * 32];   // bf16 [n][128] = 2 planes

// -------- dynamic smem ------------------------------------------------------
#define SM_E2   0
#define SM_A    3072
#define SM_B    37888
#define SMEM_TOTAL 107520

__device__ __forceinline__ uint32_t smem_u32(const void* p) {
    uint32_t a;
    asm("{ .reg .u64 t; cvta.to.shared.u64 t, %1; cvt.u32.u64 %0, t; }" : "=r"(a) : "l"(p));
    return a;
}
__device__ __forceinline__ void ldsm_x4(uint32_t* r, uint32_t addr) {
    asm volatile("ldmatrix.sync.aligned.m8n8.x4.shared.b16 {%0,%1,%2,%3}, [%4];"
                 : "=r"(r[0]), "=r"(r[1]), "=r"(r[2]), "=r"(r[3]) : "r"(addr));
}
__device__ __forceinline__ void ldsm_x2(uint32_t* r, uint32_t addr) {
    asm volatile("ldmatrix.sync.aligned.m8n8.x2.shared.b16 {%0,%1}, [%2];"
                 : "=r"(r[0]), "=r"(r[1]) : "r"(addr));
}
#define MMA(C, A, B)                                                               \
    asm volatile("mma.sync.aligned.m16n8k16.row.col.f32.bf16.bf16.f32 "            \
                 "{%0,%1,%2,%3},{%4,%5,%6,%7},{%8,%9},{%0,%1,%2,%3};"              \
                 : "+f"((C)[0]), "+f"((C)[1]), "+f"((C)[2]), "+f"((C)[3])          \
                 : "r"((A)[0]), "r"((A)[1]), "r"((A)[2]), "r"((A)[3]),             \
                   "r"((B)[0]), "r"((B)[1]))

// ============================================================================
// Kernel 0: zero scratch, split embed -> bf16x2, transpose fp32 embed, ||e||^2
// ============================================================================
__global__ void prep_kernel(const float* __restrict__ embed) {
    int t = blockIdx.x * blockDim.x + threadIdx.x;
    if (t < DDIM * KCODES) {
        float x = embed[t];                       // [d][n]
        int d = t >> 9, n = t & 511;
        #pragma unroll
        for (int p = 0; p < NPART; p++) g_esumT[p][t] = 0.0f;
        g_embT[n * 64 + d] = x;
        __nv_bfloat16 b0 = __float2bfloat16(x);
        float r1 = x - __bfloat162float(b0);
        __nv_bfloat16 b1 = __float2bfloat16(r1);
        __nv_bfloat16* eb = (__nv_bfloat16*)g_ebu;
        eb[n * 128 +      d] = b0;
        eb[n * 128 + 64 + d] = b1;
    }
    if (t < KCODES) {
        g_cnt[t] = 0.0f;
        float s = 0.0f;
        #pragma unroll 8
        for (int d = 0; d < DDIM; d++) {
            float e = embed[d * KCODES + t];
            s = fmaf(e, e, s);
        }
        g_e2[t] = s;
    }
    if (t == 0) { g_diff = 0.0; g_flagcnt = 0; }
}

// ============================================================================
// Kernel 1: phase-1 3-term HMMA distance GEMM + top-2 argmin + margin flagging
// (unchanged from R11)
// ============================================================================
__global__ __launch_bounds__(256, 2) void vq_main(const float* __restrict__ input) {
    extern __shared__ char smem[];
    const uint32_t sb = smem_u32(smem);
    float* sE2 = (float*)(smem + SM_E2);

    const int tid = threadIdx.x;
    const int wid = tid >> 5, lane = tid & 31;
    const int r0 = blockIdx.x * RB;

    sE2[tid]       = g_e2[tid];
    sE2[tid + 256] = g_e2[tid + 256];

    #pragma unroll
    for (int i = 0; i < 16; i++) {
        int e = tid + 256 * i;
        int m = e >> 5, d0 = (e & 31) * 2;
        float2 v = *(const float2*)&input[(size_t)(r0 + m) * DDIM + d0];
        __nv_bfloat16 p0a = __float2bfloat16(v.x), p0b = __float2bfloat16(v.y);
        float r1a = v.x - __bfloat162float(p0a), r1b = v.y - __bfloat162float(p0b);
        __nv_bfloat16 p1a = __float2bfloat16(r1a), p1b = __float2bfloat16(r1b);
        char* row = smem + SM_A + m * APITCH;
        *(uint32_t*)(row +       d0 * 2) = (uint32_t)__bfloat16_as_ushort(p0a) | ((uint32_t)__bfloat16_as_ushort(p0b) << 16);
        *(uint32_t*)(row + 128 + d0 * 2) = (uint32_t)__bfloat16_as_ushort(p1a) | ((uint32_t)__bfloat16_as_ushort(p1b) << 16);
    }
    __syncthreads();

    uint32_t af[8][4];
    {
        int t4 = lane >> 3, rlo = lane & 7;
        int mrow = wid * 16 + ((t4 & 1) << 3) + rlo;
        int koff = (t4 >> 1) << 3;
        #pragma unroll
        for (int p = 0; p < 2; p++)
            #pragma unroll
            for (int s = 0; s < 4; s++)
                ldsm_x4(af[p * 4 + s], sb + SM_A + mrow * APITCH + (p * 64 + s * 16 + koff) * 2);
    }

    float bv0 = FLT_MAX, sv0 = FLT_MAX, bv1 = FLT_MAX, sv1 = FLT_MAX;
    int   bk0 = 0x7fffffff, bk1 = 0x7fffffff;

    for (int chunk = 0; chunk < 2; chunk++) {
        #pragma unroll
        for (int i = 0; i < 32; i++) {
            int u = tid + 256 * i;
            int n = u >> 5, q = u & 31;
            *(unsigned long long*)(smem + SM_B + n * BPITCH + q * 8) =
                g_ebu[(size_t)(chunk * 256 + n) * 32 + q];
        }
        __syncthreads();

        for (int nt = 0; nt < 32; nt += 2) {
            uint32_t bf[2][8][2];
            {
                int rlo = lane & 7, khalf = ((lane >> 3) & 1) << 3;
                #pragma unroll
                for (int u = 0; u < 2; u++)
                    #pragma unroll
                    for (int p = 0; p < 2; p++)
                        #pragma unroll
                        for (int s = 0; s < 4; s++)
                            ldsm_x2(bf[u][p * 4 + s],
                                    sb + SM_B + ((nt + u) * 8 + rlo) * BPITCH +
                                    (p * 64 + s * 16 + khalf) * 2);
            }
            float Cc[2][2][4];
            #pragma unroll
            for (int u = 0; u < 2; u++)
                #pragma unroll
                for (int c = 0; c < 2; c++)
                    #pragma unroll
                    for (int j = 0; j < 4; j++) Cc[u][c][j] = 0.0f;

            #pragma unroll
            for (int s = 0; s < 4; s++) {
                MMA(Cc[0][0], af[s], bf[0][s]);
                MMA(Cc[0][1], af[s], bf[0][4 + s]);
                MMA(Cc[1][0], af[s], bf[1][s]);
                MMA(Cc[1][1], af[s], bf[1][4 + s]);
            }
            #pragma unroll
            for (int s = 0; s < 4; s++) {
                MMA(Cc[0][0], af[4 + s], bf[0][s]);
                MMA(Cc[1][0], af[4 + s], bf[1][s]);
            }

            #pragma unroll
            for (int u = 0; u < 2; u++) {
                int nb = chunk * 256 + (nt + u) * 8 + 2 * (lane & 3);
                float e2a = sE2[nb], e2b = sE2[nb + 1];
                float d00 = e2a - 2.0f * (Cc[u][0][0] + Cc[u][1][0]);
                float d01 = e2b - 2.0f * (Cc[u][0][1] + Cc[u][1][1]);
                float d10 = e2a - 2.0f * (Cc[u][0][2] + Cc[u][1][2]);
                float d11 = e2b - 2.0f * (Cc[u][0][3] + Cc[u][1][3]);
                if (d00 < bv0) { sv0 = bv0; bv0 = d00; bk0 = nb; } else if (d00 < sv0) sv0 = d00;
                if (d01 < bv0) { sv0 = bv0; bv0 = d01; bk0 = nb + 1; } else if (d01 < sv0) sv0 = d01;
                if (d10 < bv1) { sv1 = bv1; bv1 = d10; bk1 = nb; } else if (d10 < sv1) sv1 = d10;
                if (d11 < bv1) { sv1 = bv1; bv1 = d11; bk1 = nb + 1; } else if (d11 < sv1) sv1 = d11;
            }
        }
        __syncthreads();
    }

    #pragma unroll
    for (int off = 1; off <= 2; off <<= 1) {
        float ov0 = __shfl_xor_sync(0xffffffffu, bv0, off);
        int   ok0 = __shfl_xor_sync(0xffffffffu, bk0, off);
        float os0 = __shfl_xor_sync(0xffffffffu, sv0, off);
        float ov1 = __shfl_xor_sync(0xffffffffu, bv1, off);
        int   ok1 = __shfl_xor_sync(0xffffffffu, bk1, off);
        float os1 = __shfl_xor_sync(0xffffffffu, sv1, off);
        if (ov0 < bv0 || (ov0 == bv0 && ok0 < bk0)) { sv0 = fminf(bv0, os0); bv0 = ov0; bk0 = ok0; }
        else sv0 = fminf(sv0, fminf(ov0, os0));
        if (ov1 < bv1 || (ov1 == bv1 && ok1 < bk1)) { sv1 = fminf(bv1, os1); bv1 = ov1; bk1 = ok1; }
        else sv1 = fminf(sv1, fminf(ov1, os1));
    }
    if ((lane & 3) == 0) {
        int rq = r0 + wid * 16 + (lane >> 2);
        g_kbest[rq] = bk0;
        if (sv0 - bv0 <= MARGIN) g_flagrows[atomicAdd(&g_flagcnt, 1)] = rq;
        g_kbest[rq + 8] = bk1;
        if (sv1 - bv1 <= MARGIN) g_flagrows[atomicAdd(&g_flagcnt, 1)] = rq + 8;
    }
}

// ============================================================================
// Kernel 2: rescue — exact fp32 argmin for flagged rows (unchanged)
// ============================================================================
__global__ void rescue_kernel(const float* __restrict__ input,
                              const float* __restrict__ embed) {
    const int lane = threadIdx.x & 31;
    const int gw = blockIdx.x * (blockDim.x >> 5) + (threadIdx.x >> 5);
    const int nw = gridDim.x * (blockDim.x >> 5);
    const int nflag = g_flagcnt;

    for (int i = gw; i < nflag; i += nw) {
        int row = g_flagrows[i];
        float xa = input[(size_t)row * DDIM + lane];
        float xb = input[(size_t)row * DDIM + 32 + lane];
        float acc[16];
        #pragma unroll
        for (int j = 0; j < 16; j++) acc[j] = 0.0f;
        for (int d = 0; d < DDIM; d++) {
            float xd = (d < 32) ? __shfl_sync(0xffffffffu, xa, d)
                                : __shfl_sync(0xffffffffu, xb, d - 32);
            const float* er = embed + d * KCODES + lane;
            #pragma unroll
            for (int j = 0; j < 16; j++) acc[j] = fmaf(xd, er[32 * j], acc[j]);
        }
        float bv = FLT_MAX; int bk = 0x7fffffff;
        #pragma unroll
        for (int j = 0; j < 16; j++) {
            int k = lane + 32 * j;
            float dist = g_e2[k] - 2.0f * acc[j];
            if (dist < bv) { bv = dist; bk = k; }
        }
        #pragma unroll
        for (int off = 16; off; off >>= 1) {
            float ov = __shfl_xor_sync(0xffffffffu, bv, off);
            int   ok = __shfl_xor_sync(0xffffffffu, bk, off);
            if (ov < bv || (ov == bv && ok < bk)) { bv = ov; bk = ok; }
        }
        if (lane == 0) g_kbest[row] = bk;
    }
}

// ============================================================================
// Kernel 3: epilogue — float4 everything, partitioned vector atomics
//   warp: 16 lanes per row, 2 rows per pass, 8 rows total
// ============================================================================
__global__ void epilogue_kernel(const float* __restrict__ input,
                                float* __restrict__ out) {
    const int lane = threadIdx.x & 31;
    const int gw = blockIdx.x * 8 + (threadIdx.x >> 5);
    const int half = lane >> 4, sl = lane & 15;
    const int part = blockIdx.x & (NPART - 1);
    double dsum = 0.0;

    #pragma unroll
    for (int j = 0; j < 4; j++) {
        int row = gw * 8 + j * 2 + half;
        int kbest = g_kbest[row];
        float4 x = *(const float4*)&input[(size_t)row * DDIM + sl * 4];
        float4 q = *(const float4*)&g_embT[kbest * DDIM + sl * 4];
        float4 qst;
        qst.x = x.x + (q.x - x.x); qst.y = x.y + (q.y - x.y);
        qst.z = x.z + (q.z - x.z); qst.w = x.w + (q.w - x.w);
        *(float4*)&out[OFF_Q + (size_t)row * DDIM + sl * 4] = qst;
        float dx = q.x - x.x, dy = q.y - x.y, dz = q.z - x.z, dw = q.w - x.w;
        dsum += (double)dx * dx + (double)dy * dy + (double)dz * dz + (double)dw * dw;
#if defined(__CUDA_ARCH__) && __CUDA_ARCH__ >= 900
        atomicAdd((float4*)&g_esumT[part][kbest * DDIM + sl * 4], x);
#else
        atomicAdd(&g_esumT[part][kbest * DDIM + sl * 4 + 0], x.x);
        atomicAdd(&g_esumT[part][kbest * DDIM + sl * 4 + 1], x.y);
        atomicAdd(&g_esumT[part][kbest * DDIM + sl * 4 + 2], x.z);
        atomicAdd(&g_esumT[part][kbest * DDIM + sl * 4 + 3], x.w);
#endif
        if (sl == 0) {
            out[OFF_IND + row] = (float)kbest;
            atomicAdd(&g_cnt[kbest], 1.0f);
        }
    }
    #pragma unroll
    for (int off = 16; off; off >>= 1)
        dsum += __shfl_xor_sync(0xffffffffu, dsum, off);
    if (lane == 0) atomicAdd(&g_diff, dsum);
}

// ============================================================================
// Kernel 4: EMA update + normalize + diff mean (reads transposed partitions)
// ============================================================================
__global__ void vq_finalize(const float* __restrict__ cluster_size,
                            const float* __restrict__ embed_avg,
                            float* __restrict__ out) {
    __shared__ float red[512];
    const int k = threadIdx.x;
    const float DEC = 0.99f;
    const float OMD = (float)(1.0 - 0.99);

    float ncs = cluster_size[k] * DEC + OMD * g_cnt[k];
    out[OFF_NCS + k] = ncs;
    red[k] = ncs;
    __syncthreads();
    for (int s = 256; s; s >>= 1) {
        if (k < s) red[k] += red[k + s];
        __syncthreads();
    }
    float n  = red[0];
    float cs = (ncs + 1e-5f) / (n + 512.0f * 1e-5f) * n;

    for (int d = 0; d < DDIM; d++) {
        int idx = d * KCODES + k;
        float es = g_esumT[0][k * DDIM + d] + g_esumT[1][k * DDIM + d] +
                   g_esumT[2][k * DDIM + d] + g_esumT[3][k * DDIM + d];
        float nea = embed_avg[idx] * DEC + OMD * es;
        out[OFF_NEA + idx] = nea;
        out[OFF_EN  + idx] = nea / cs;
    }
    if (k == 0) out[OFF_DIFF] = (float)(g_diff * (1.0 / 4194304.0));
}

// ============================================================================
extern "C" void kernel_launch(void* const* d_in, const int* in_sizes, int n_in,
                              void* d_out, int out_size) {
    const float* input        = (const float*)d_in[0];
    const float* embed        = (const float*)d_in[1];
    const float* cluster_size = (const float*)d_in[2];
    const float* embed_avg    = (const float*)d_in[3];
    float* out = (float*)d_out;

    cudaFuncSetAttribute(vq_main, cudaFuncAttributeMaxDynamicSharedMemorySize, SMEM_TOTAL);
    prep_kernel<<<128, 256>>>(embed);
    vq_main<<<512, 256, SMEM_TOTAL>>>(input);
    rescue_kernel<<<256, 256>>>(input, embed);
    epilogue_kernel<<<1024, 256>>>(input, out);
    vq_finalize<<<1, 512>>>(cluster_size, embed_avg, out);
}